// round 14
// baseline (speedup 1.0000x reference)
#include <cuda_runtime.h>
#include <cuda_bf16.h>
#include <cstdint>
#include <math.h>

// Problem constants
#define BSZ   64
#define SLEN  4096
#define EMB   266
#define HID   512
#define NH    128
#define ROWS  (BSZ * NH)   // 8192
#define URows (NH + BSZ)   // 192

// mma.sync GEMM tiling
#define TILE_M 128
#define TILE_N 128
#define BK     32                 // K chunk per stage
#define NCHUNK (HID / BK)         // 16
#define LDT    40                 // smem row stride in bf16 (32 + 8 pad)
#define LDTB   (LDT * 2)          // 80 bytes
#define TILEB  (128 * LDTB)       // 10240 bytes per operand tile
#define SM_BIAS_BYTES 512
#define SM_TOTAL (SM_BIAS_BYTES + 8 * TILEB)   // 82432
#define NPART  16                 // 4 nt tiles x 4 warp-columns

// Static device scratch (no allocations allowed)
__device__ float g_UV[URows * HID];
__device__ float g_coef[ROWS * 2];
__device__ float g_part[NPART * ROWS * 2];      // per-(nt,wn) out_proj partials
__device__ __nv_bfloat16 g_Ah[2][ROWS * HID];   // activation hi, ping/pong
__device__ __nv_bfloat16 g_Al[2][ROWS * HID];   // activation lo
__device__ __nv_bfloat16 g_Wh[3 * HID * HID];   // weights hi, [l][n][k]
__device__ __nv_bfloat16 g_Wl[3 * HID * HID];   // weights lo

__device__ __forceinline__ float silu_f(float v) {
    return v * (1.0f / (1.0f + __expf(-v)));
}

__device__ __forceinline__ uint32_t smem_u32(const void* p) {
    uint32_t a;
    asm("{ .reg .u64 t; cvta.to.shared.u64 t, %1; cvt.u32.u64 %0, t; }" : "=r"(a) : "l"(p));
    return a;
}

// ---------------- sm_80-class primitives (no 'a'-suffix features) ----------
#define CP_ASYNC16(dst, src) \
    asm volatile("cp.async.cg.shared.global [%0], [%1], 16;" :: "r"(dst), "l"(src))
#define CP_COMMIT() asm volatile("cp.async.commit_group;" ::: "memory")
#define CP_WAIT(n)  asm volatile("cp.async.wait_group %0;" :: "n"(n) : "memory")

#define LDSM4(r, addr)                                                         \
    asm volatile("ldmatrix.sync.aligned.m8n8.x4.shared.b16 {%0,%1,%2,%3}, [%4];" \
        : "=r"((r)[0]), "=r"((r)[1]), "=r"((r)[2]), "=r"((r)[3]) : "r"(addr))
#define LDSM2(r, addr)                                                         \
    asm volatile("ldmatrix.sync.aligned.m8n8.x2.shared.b16 {%0,%1}, [%2];"     \
        : "=r"((r)[0]), "=r"((r)[1]) : "r"(addr))

#define MMA_BF16(d, a, b)                                                      \
    asm volatile("mma.sync.aligned.m16n8k16.row.col.f32.bf16.bf16.f32 "        \
        "{%0,%1,%2,%3}, {%4,%5,%6,%7}, {%8,%9}, {%0,%1,%2,%3};"                \
        : "+f"((d)[0]), "+f"((d)[1]), "+f"((d)[2]), "+f"((d)[3])               \
        : "r"((a)[0]), "r"((a)[1]), "r"((a)[2]), "r"((a)[3]),                  \
          "r"((b)[0]), "r"((b)[1]))

// Stage one 128x32 bf16 tile (global row stride HID) into padded smem rows.
__device__ __forceinline__ void stage_in(uint32_t sbase,
                                         const __nv_bfloat16* __restrict__ g,
                                         int tid) {
    #pragma unroll
    for (int it = 0; it < 2; it++) {
        int idx = tid + it * 256;      // 0..511
        int row = idx >> 2;            // 0..127
        int seg = idx & 3;             // 16B segment within the 64B row chunk
        uint32_t dst = sbase + row * LDTB + seg * 16;
        const __nv_bfloat16* src = g + (size_t)row * HID + seg * 8;
        CP_ASYNC16(dst, src);
    }
}

#define TOFF(s, o) (SM_BIAS_BYTES + ((s) * 4 + (o)) * TILEB)

// Shared bf16x3 mainloop: fills acc[4][4][4] with A @ B^T in fp32.
__device__ __forceinline__ void mma_mainloop(
    uint32_t sb,
    const __nv_bfloat16* __restrict__ aH, const __nv_bfloat16* __restrict__ aL,
    const __nv_bfloat16* __restrict__ bH, const __nv_bfloat16* __restrict__ bL,
    int tid, float acc[4][4][4]) {
    const int lane = tid & 31;
    const int wid = tid >> 5;
    const int wm = wid & 1;
    const int wn = wid >> 1;

    // Prefetch stage 0
    stage_in(sb + TOFF(0, 0), aH, tid);
    stage_in(sb + TOFF(0, 1), aL, tid);
    stage_in(sb + TOFF(0, 2), bH, tid);
    stage_in(sb + TOFF(0, 3), bL, tid);
    CP_COMMIT();

    const int amat = lane >> 3;
    const int arow = (lane & 7) + (amat & 1) * 8;
    const int akb  = (amat >> 1) * 16;
    const int bidx = lane & 15;
    const int brow = bidx & 7;
    const int bkb  = (bidx >> 3) * 16;

    for (int c = 0; c < NCHUNK; c++) {
        const int cur = c & 1;
        if (c + 1 < NCHUNK) {
            const int k0 = (c + 1) * BK;
            const int nx = cur ^ 1;
            stage_in(sb + TOFF(nx, 0), aH + k0, tid);
            stage_in(sb + TOFF(nx, 1), aL + k0, tid);
            stage_in(sb + TOFF(nx, 2), bH + k0, tid);
            stage_in(sb + TOFF(nx, 3), bL + k0, tid);
            CP_COMMIT();
            CP_WAIT(1);
        } else {
            CP_WAIT(0);
        }
        __syncthreads();

        const uint32_t sAh = sb + TOFF(cur, 0);
        const uint32_t sAl = sb + TOFF(cur, 1);
        const uint32_t sBh = sb + TOFF(cur, 2);
        const uint32_t sBl = sb + TOFF(cur, 3);

        #pragma unroll
        for (int ks = 0; ks < 2; ks++) {
            uint32_t ah[4][4], al[4][4], bh2[4][2], bl2[4][2];
            const int kb = ks * 32;
            #pragma unroll
            for (int mi = 0; mi < 4; mi++) {
                uint32_t off = (uint32_t)((wm * 64 + mi * 16 + arow) * LDTB + kb + akb);
                LDSM4(ah[mi], sAh + off);
                LDSM4(al[mi], sAl + off);
            }
            #pragma unroll
            for (int nj = 0; nj < 4; nj++) {
                uint32_t off = (uint32_t)((wn * 32 + nj * 8 + brow) * LDTB + kb + bkb);
                LDSM2(bh2[nj], sBh + off);
                LDSM2(bl2[nj], sBl + off);
            }
            #pragma unroll
            for (int mi = 0; mi < 4; mi++)
                #pragma unroll
                for (int nj = 0; nj < 4; nj++) {
                    MMA_BF16(acc[mi][nj], ah[mi], bh2[nj]);   // hi*hi
                    MMA_BF16(acc[mi][nj], al[mi], bh2[nj]);   // lo*hi
                    MMA_BF16(acc[mi][nj], ah[mi], bl2[nj]);   // hi*lo
                }
        }
        __syncthreads();
    }
}

// ---------------------------------------------------------------------------
// Hidden layers 1-2: C = silu(A @ B^T + bias), output re-split to hi/lo bf16.
// Grid (4, 64) = (nt, mt); 256 threads = 8 warps (2 M x 4 N), warp tile 64x32.
// ---------------------------------------------------------------------------
__global__ void __launch_bounds__(256)
gemm_mma(const __nv_bfloat16* __restrict__ Ah, const __nv_bfloat16* __restrict__ Al,
         const __nv_bfloat16* __restrict__ Bh, const __nv_bfloat16* __restrict__ Bl,
         const float* __restrict__ bias,
         __nv_bfloat16* __restrict__ Ch, __nv_bfloat16* __restrict__ Cl) {
    extern __shared__ char smem[];
    const uint32_t sb = smem_u32(smem);
    float* sBias = reinterpret_cast<float*>(smem);

    const int tid = threadIdx.x;
    const int lane = tid & 31;
    const int wid = tid >> 5;
    const int wm = wid & 1, wn = wid >> 1;
    const int nt = blockIdx.x, mt = blockIdx.y;

    if (tid < TILE_N) sBias[tid] = bias[nt * TILE_N + tid];

    float acc[4][4][4] = {};
    mma_mainloop(sb,
                 Ah + (size_t)(mt * TILE_M) * HID, Al + (size_t)(mt * TILE_M) * HID,
                 Bh + (size_t)(nt * TILE_N) * HID, Bl + (size_t)(nt * TILE_N) * HID,
                 tid, acc);

    // Epilogue: bias + silu, re-split to hi/lo bf16
    const int lm = lane >> 2, ln = lane & 3;
    #pragma unroll
    for (int mi = 0; mi < 4; mi++) {
        #pragma unroll
        for (int nj = 0; nj < 4; nj++) {
            const float* a = acc[mi][nj];
            const int row  = mt * TILE_M + wm * 64 + mi * 16 + lm;
            const int colL = wn * 32 + nj * 8 + ln * 2;
            const int col  = nt * TILE_N + colL;
            const float b0 = sBias[colL], b1 = sBias[colL + 1];
            #pragma unroll
            for (int half = 0; half < 2; half++) {
                const int r = row + half * 8;
                const float v0 = silu_f(a[half * 2 + 0] + b0);
                const float v1 = silu_f(a[half * 2 + 1] + b1);
                __nv_bfloat16 h0 = __float2bfloat16(v0);
                __nv_bfloat16 h1 = __float2bfloat16(v1);
                __nv_bfloat162 hp, lp;
                hp.x = h0; hp.y = h1;
                lp.x = __float2bfloat16(v0 - __bfloat162float(h0));
                lp.y = __float2bfloat16(v1 - __bfloat162float(h1));
                const size_t o = (size_t)r * HID + col;
                *reinterpret_cast<__nv_bfloat162*>(Ch + o) = hp;
                *reinterpret_cast<__nv_bfloat162*>(Cl + o) = lp;
            }
        }
    }
}

// ---------------------------------------------------------------------------
// Layer 3 fused with output projection: dot silu(acc+bias) rows against
// w_out[:,0:2]; each (nt, wn) pair owns a distinct partial slot (no races).
// ---------------------------------------------------------------------------
__global__ void __launch_bounds__(256)
gemm_mma_out(const __nv_bfloat16* __restrict__ Ah, const __nv_bfloat16* __restrict__ Al,
             const __nv_bfloat16* __restrict__ Bh, const __nv_bfloat16* __restrict__ Bl,
             const float* __restrict__ bias, const float* __restrict__ w_out) {
    extern __shared__ char smem[];
    const uint32_t sb = smem_u32(smem);
    float* sBias = reinterpret_cast<float*>(smem);

    const int tid = threadIdx.x;
    const int lane = tid & 31;
    const int wid = tid >> 5;
    const int wm = wid & 1, wn = wid >> 1;
    const int nt = blockIdx.x, mt = blockIdx.y;

    if (tid < TILE_N) sBias[tid] = bias[nt * TILE_N + tid];

    float acc[4][4][4] = {};
    mma_mainloop(sb,
                 Ah + (size_t)(mt * TILE_M) * HID, Al + (size_t)(mt * TILE_M) * HID,
                 Bh + (size_t)(nt * TILE_N) * HID, Bl + (size_t)(nt * TILE_N) * HID,
                 tid, acc);

    // Epilogue: silu + dot with w_out, lane-reduce over the 4 N-lanes.
    const int lm = lane >> 2, ln = lane & 3;
    const size_t pslot = (size_t)(nt * 4 + wn) * ROWS;   // distinct per (nt, wn)
    #pragma unroll
    for (int mi = 0; mi < 4; mi++) {
        float sA = 0.f, cA = 0.f;   // row = base
        float sB = 0.f, cB = 0.f;   // row = base + 8
        #pragma unroll
        for (int nj = 0; nj < 4; nj++) {
            const float* a = acc[mi][nj];
            const int colL = wn * 32 + nj * 8 + ln * 2;
            const int col  = nt * TILE_N + colL;
            const float b0 = sBias[colL], b1 = sBias[colL + 1];
            const float w00 = __ldg(w_out + 2 * col + 0);
            const float w01 = __ldg(w_out + 2 * col + 1);
            const float w10 = __ldg(w_out + 2 * col + 2);
            const float w11 = __ldg(w_out + 2 * col + 3);
            float v0 = silu_f(a[0] + b0), v1 = silu_f(a[1] + b1);
            sA = fmaf(v0, w00, fmaf(v1, w10, sA));
            cA = fmaf(v0, w01, fmaf(v1, w11, cA));
            float v2 = silu_f(a[2] + b0), v3 = silu_f(a[3] + b1);
            sB = fmaf(v2, w00, fmaf(v3, w10, sB));
            cB = fmaf(v2, w01, fmaf(v3, w11, cB));
        }
        #pragma unroll
        for (int o = 1; o < 4; o <<= 1) {
            sA += __shfl_xor_sync(0xffffffffu, sA, o);
            cA += __shfl_xor_sync(0xffffffffu, cA, o);
            sB += __shfl_xor_sync(0xffffffffu, sB, o);
            cB += __shfl_xor_sync(0xffffffffu, cB, o);
        }
        if (ln == 0) {
            const int r = mt * TILE_M + wm * 64 + mi * 16 + lm;
            g_part[(pslot + r) * 2 + 0]     = sA;
            g_part[(pslot + r) * 2 + 1]     = cA;
            g_part[(pslot + r + 8) * 2 + 0] = sB;
            g_part[(pslot + r + 8) * 2 + 1] = cB;
        }
    }
}

// ---------------------------------------------------------------------------
// Reduce the 16 per-(nt,wn) partials into final coefficients (+ b_out)
// ---------------------------------------------------------------------------
__global__ void coef_reduce(const float* __restrict__ b_out) {
    int r = blockIdx.x * blockDim.x + threadIdx.x;
    if (r >= ROWS) return;
    float s = b_out[0], c = b_out[1];
    #pragma unroll
    for (int p = 0; p < NPART; p++) {
        s += g_part[((size_t)p * ROWS + r) * 2 + 0];
        c += g_part[((size_t)p * ROWS + r) * 2 + 1];
    }
    g_coef[2 * r + 0] = s;
    g_coef[2 * r + 1] = c;
}

// ---------------------------------------------------------------------------
// Weight prep: g_W{h,l}[l][n][k] = split(w_h[l][k][n])  (transpose + bf16 split)
// ---------------------------------------------------------------------------
__global__ void wprep(const float* __restrict__ w_h) {
    int idx = blockIdx.x * blockDim.x + threadIdx.x;
    if (idx >= 3 * HID * HID) return;
    int l = idx >> 18;
    int rem = idx & (HID * HID - 1);
    int n = rem >> 9, k = rem & 511;
    float v = w_h[(size_t)l * HID * HID + (size_t)k * HID + n];
    __nv_bfloat16 h = __float2bfloat16(v);
    g_Wh[idx] = h;
    g_Wl[idx] = __float2bfloat16(v - __bfloat162float(h));
}

// ---------------------------------------------------------------------------
// Input projection (rank-structured layer 0): UV[r] = (emb|z)[r] @ w_in
// ---------------------------------------------------------------------------
__global__ void __launch_bounds__(256)
in_gemm(const float* __restrict__ z, const float* __restrict__ emb,
        const float* __restrict__ w_in) {
    __shared__ float row[EMB];
    const int r = blockIdx.x;
    const float* src = (r < NH) ? (emb + (size_t)r * EMB)
                                : (z + (size_t)(r - NH) * EMB);
    for (int k = threadIdx.x; k < EMB; k += 256) row[k] = src[k];
    __syncthreads();

    const int c = threadIdx.x;
    float a0 = 0.f, a1 = 0.f;
    #pragma unroll 2
    for (int k = 0; k < EMB; k++) {
        float rv = row[k];
        a0 = fmaf(rv, w_in[(size_t)k * HID + c],       a0);
        a1 = fmaf(rv, w_in[(size_t)k * HID + c + 256], a1);
    }
    g_UV[(size_t)r * HID + c]       = a0;
    g_UV[(size_t)r * HID + c + 256] = a1;
}

// ---------------------------------------------------------------------------
// Combine: H0 = silu(UV[h] + UV[128+b] + b_in), written as bf16 hi/lo
// ---------------------------------------------------------------------------
__global__ void __launch_bounds__(256)
combine_kernel(const float* __restrict__ b_in) {
    int idx4 = blockIdx.x * blockDim.x + threadIdx.x;
    int c4 = idx4 & (HID / 4 - 1);
    int r  = idx4 >> 7;
    int b = r >> 7, h = r & 127;

    float4 u = *reinterpret_cast<const float4*>(&g_UV[(size_t)h * HID + c4 * 4]);
    float4 v = *reinterpret_cast<const float4*>(&g_UV[(size_t)(NH + b) * HID + c4 * 4]);
    float4 bb = *reinterpret_cast<const float4*>(&b_in[c4 * 4]);
    float o[4];
    o[0] = silu_f(u.x + v.x + bb.x);
    o[1] = silu_f(u.y + v.y + bb.y);
    o[2] = silu_f(u.z + v.z + bb.z);
    o[3] = silu_f(u.w + v.w + bb.w);

    size_t base = (size_t)r * HID + c4 * 4;
    #pragma unroll
    for (int i = 0; i < 4; i += 2) {
        __nv_bfloat16 h0 = __float2bfloat16(o[i]);
        __nv_bfloat16 h1 = __float2bfloat16(o[i + 1]);
        __nv_bfloat162 hp, lp;
        hp.x = h0; hp.y = h1;
        lp.x = __float2bfloat16(o[i]     - __bfloat162float(h0));
        lp.y = __float2bfloat16(o[i + 1] - __bfloat162float(h1));
        *reinterpret_cast<__nv_bfloat162*>(&g_Ah[0][base + i]) = hp;
        *reinterpret_cast<__nv_bfloat162*>(&g_Al[0][base + i]) = lp;
    }
}

// ---------------------------------------------------------------------------
// Fourier synthesis: FREQS = 1..128 -> one sincos + two interleaved
// angle-addition chains stepping by the double angle (halves the dep chain).
// ---------------------------------------------------------------------------
__global__ void __launch_bounds__(256)
synth_kernel(const float* __restrict__ target_x, float* __restrict__ out) {
    __shared__ float sc[NH], cc[NH];
    const int b = blockIdx.y;
    const int t = threadIdx.x;
    if (t < NH) {
        float2 v = *reinterpret_cast<const float2*>(&g_coef[(b * NH + t) * 2]);
        sc[t] = v.x;
        cc[t] = v.y;
    }
    __syncthreads();

    const int s = blockIdx.x * blockDim.x + t;
    float xv = target_x[b * SLEN + s];
    float theta = 6.283185307179586f * xv;
    float s1, c1;
    sincosf(theta, &s1, &c1);
    const float c2 = 1.0f - 2.0f * s1 * s1;   // cos 2θ
    const float s2 = 2.0f * s1 * c1;          // sin 2θ

    float cA = c1, sA = s1;   // odd harmonics 1,3,5,...
    float cB = c2, sB = s2;   // even harmonics 2,4,6,...
    float accA = 0.f, accB = 0.f;
    #pragma unroll 8
    for (int i = 0; i < NH / 2; i++) {
        accA = fmaf(cA, cc[2 * i],     accA);
        accA = fmaf(sA, sc[2 * i],     accA);
        accB = fmaf(cB, cc[2 * i + 1], accB);
        accB = fmaf(sB, sc[2 * i + 1], accB);
        float ncA = fmaf(cA, c2, -sA * s2);
        float nsA = fmaf(sA, c2,  cA * s2);
        float ncB = fmaf(cB, c2, -sB * s2);
        float nsB = fmaf(sB, c2,  cB * s2);
        cA = ncA; sA = nsA; cB = ncB; sB = nsB;
    }
    out[b * SLEN + s] = accA + accB;
}

// ---------------------------------------------------------------------------
// Launch sequence
// ---------------------------------------------------------------------------
extern "C" void kernel_launch(void* const* d_in, const int* in_sizes, int n_in,
                              void* d_out, int out_size) {
    const float* target_x = (const float*)d_in[0];
    const float* z        = (const float*)d_in[1];
    const float* emb      = (const float*)d_in[3];
    const float* w_in     = (const float*)d_in[4];
    const float* b_in     = (const float*)d_in[5];
    const float* w_h      = (const float*)d_in[6];
    const float* b_h      = (const float*)d_in[7];
    const float* w_out    = (const float*)d_in[8];
    const float* b_out    = (const float*)d_in[9];
    float* out = (float*)d_out;

    __nv_bfloat16 *Ah, *Al, *Wh, *Wl;
    cudaGetSymbolAddress((void**)&Ah, g_Ah);
    cudaGetSymbolAddress((void**)&Al, g_Al);
    cudaGetSymbolAddress((void**)&Wh, g_Wh);
    cudaGetSymbolAddress((void**)&Wl, g_Wl);
    __nv_bfloat16* Ah1 = Ah + (size_t)ROWS * HID;
    __nv_bfloat16* Al1 = Al + (size_t)ROWS * HID;

    // Idempotent; called every time (no static guards allowed).
    cudaFuncSetAttribute(gemm_mma,     cudaFuncAttributeMaxDynamicSharedMemorySize, SM_TOTAL);
    cudaFuncSetAttribute(gemm_mma_out, cudaFuncAttributeMaxDynamicSharedMemorySize, SM_TOTAL);

    // 1) weight split/transpose + input projection
    wprep<<<(3 * HID * HID + 255) / 256, 256>>>(w_h);
    in_gemm<<<URows, 256>>>(z, emb, w_in);

    // 2) combine -> hi/lo activations (buf 0)
    combine_kernel<<<(ROWS * HID / 4) / 256, 256>>>(b_in);

    // 3) hidden layers on tensor cores (bf16x3 split, fp32 accumulate);
    //    layer 3 fused with the output projection
    dim3 gg(HID / TILE_N, ROWS / TILE_M);   // (4, 64)
    gemm_mma    <<<gg, 256, SM_TOTAL>>>(Ah,  Al,  Wh,             Wl,             b_h,       Ah1, Al1);
    gemm_mma    <<<gg, 256, SM_TOTAL>>>(Ah1, Al1, Wh + HID * HID, Wl + HID * HID, b_h + HID, Ah,  Al);
    gemm_mma_out<<<gg, 256, SM_TOTAL>>>(Ah,  Al,  Wh + 2 * HID * HID, Wl + 2 * HID * HID,
                                        b_h + 2 * HID, w_out);

    // 4) reduce partials -> coefficients
    coef_reduce<<<(ROWS + 255) / 256, 256>>>(b_out);

    // 5) Fourier synthesis
    dim3 sg(SLEN / 256, BSZ);
    synth_kernel<<<sg, 256>>>(target_x, out);
}